// round 5
// baseline (speedup 1.0000x reference)
#include <cuda_runtime.h>
#include <cuda_bf16.h>

// KPConv, sparsity-exact, SINGLE persistent kernel with device grid barrier:
//   phase 1 pack:   s_pack[s]=(x,y,z,rowsum), counters reset, shadow row
//   phase 2 detect: 2 queries/warp-iter -> hit records {n,si,w*inv} binned by p
//   phase 3 matvec: blocks keyed by p, W half-cached in regs, atomic accumulate
// Grid = 444 blocks @ __launch_bounds__(256,3): >= 3 blocks/SM guaranteed by
// the compiler bound and 444 <= 3*148 <= 3*152, so all blocks are co-resident
// and the spin barrier is deadlock-free.

#define N_SUP   40000
#define N_QRY   40000
#define KNBR    32
#define NKP     15
#define IN_DIM  64
#define OUT_DIM 128
#define KP_EXT  0.05f
#define THRESH  (KP_EXT * KP_EXT)
#define HITCAP  8192
#define NBLOCKS 444
#define NWARPS  (NBLOCKS * 8)

__device__ float4 g_spack[N_SUP + 1];
__device__ int    g_cnt[NKP];
__device__ int4   g_recs[NKP][HITCAP];   // {n, si, w_bits, pad}
__device__ unsigned          g_bar_count = 0;
__device__ volatile unsigned g_bar_phase = 0;

__device__ __forceinline__ void grid_barrier() {
    __syncthreads();
    if (threadIdx.x == 0) {
        unsigned ph = g_bar_phase;
        __threadfence();                       // publish this block's stores
        if (atomicAdd(&g_bar_count, 1u) == NBLOCKS - 1) {
            g_bar_count = 0;
            __threadfence();
            g_bar_phase = ph + 1;              // release
        } else {
            while (g_bar_phase == ph) __nanosleep(64);
        }
        __threadfence();                       // acquire
    }
    __syncthreads();
}

__global__ void __launch_bounds__(256, 3) kpconv_fused(
    const float* __restrict__ q_pts,
    const float* __restrict__ s_pts,
    const int*   __restrict__ nidx,
    const float* __restrict__ x,
    const float* __restrict__ wts,
    const float* __restrict__ kpts,
    float*       __restrict__ out)
{
    const unsigned FULL = 0xffffffffu;
    __shared__ float4 skp[NKP];
    __shared__ float  sR2max;

    const int tid  = threadIdx.x;
    const int lane = tid & 31;
    const int gw   = blockIdx.x * 8 + (tid >> 5);

    // ---- setup (per block; block 0 also resets globals) ----
    if (tid < NKP) {
        float a = kpts[tid * 3 + 0], b = kpts[tid * 3 + 1], c = kpts[tid * 3 + 2];
        skp[tid] = make_float4(2.0f * a, 2.0f * b, 2.0f * c, a * a + b * b + c * c);
    }
    if (blockIdx.x == 0 && tid == 0) {
        g_spack[N_SUP] = make_float4(1e9f, 1e9f, 1e9f, 0.0f);
#pragma unroll
        for (int p = 0; p < NKP; p++) g_cnt[p] = 0;
    }
    __syncthreads();
    if (tid == 0) {
        float m2 = 0.0f;
#pragma unroll
        for (int p = 0; p < NKP; p++) m2 = fmaxf(m2, skp[p].w);
        float Rb = sqrtf(m2) + KP_EXT;
        sR2max = Rb * Rb;
    }
    __syncthreads();

    // ---- phase 1: pack (8 rows per warp-iter, 16-lane segmented reduce) ----
    const float4* X4 = (const float4*)x;
    for (int c = gw; c < N_SUP / 8; c += NWARPS) {
        int base = c * 8;
        float s[4];
#pragma unroll
        for (int j = 0; j < 4; j++) {
            float4 v = X4[(size_t)(base + 2 * j) * 16 + lane];
            s[j] = (v.x + v.y) + (v.z + v.w);
        }
#pragma unroll
        for (int j = 0; j < 4; j++) {
#pragma unroll
            for (int o = 8; o; o >>= 1) s[j] += __shfl_xor_sync(FULL, s[j], o);
            if ((lane & 15) == 0) {
                int r = base + 2 * j + (lane >> 4);
                g_spack[r] = make_float4(s_pts[r * 3 + 0], s_pts[r * 3 + 1],
                                         s_pts[r * 3 + 2], s[j]);
            }
        }
    }

    grid_barrier();

    // ---- phase 2: detect (2 queries per warp-iter) ----
    const float R2max = sR2max;
    for (int q = gw; q < N_QRY / 2; q += NWARPS) {
        const int n0 = 2 * q, n1 = n0 + 1;

        const int    idx0 = nidx[(size_t)n0 * KNBR + lane];
        const int    idx1 = nidx[(size_t)n1 * KNBR + lane];
        const float4 sp0  = g_spack[idx0];
        const float4 sp1  = g_spack[idx1];

        const float qx0 = q_pts[n0 * 3 + 0], qy0 = q_pts[n0 * 3 + 1], qz0 = q_pts[n0 * 3 + 2];
        const float qx1 = q_pts[n1 * 3 + 0], qy1 = q_pts[n1 * 3 + 1], qz1 = q_pts[n1 * 3 + 2];

        const float dx0 = sp0.x - qx0, dy0 = sp0.y - qy0, dz0 = sp0.z - qz0;
        const float dx1 = sp1.x - qx1, dy1 = sp1.y - qy1, dz1 = sp1.z - qz1;
        const float r20 = fmaf(dx0, dx0, fmaf(dy0, dy0, dz0 * dz0));
        const float r21 = fmaf(dx1, dx1, fmaf(dy1, dy1, dz1 * dz1));
        const float rhs0 = r20 - THRESH;
        const float rhs1 = r21 - THRESH;

        unsigned hits0 = 0, hits1 = 0;
        bool any0 = __ballot_sync(FULL, r20 < R2max) != 0;
        bool any1 = __ballot_sync(FULL, r21 < R2max) != 0;
        if (any0 || any1) {
#pragma unroll
            for (int p = 0; p < NKP; p++) {
                float4 kk = skp[p];
                float  t0 = fmaf(dx0, kk.x, fmaf(dy0, kk.y, fmaf(dz0, kk.z, -kk.w)));
                float  t1 = fmaf(dx1, kk.x, fmaf(dy1, kk.y, fmaf(dz1, kk.z, -kk.w)));
                if (t0 > rhs0) hits0 |= (1u << p);
                if (t1 > rhs1) hits1 |= (1u << p);
            }
        }

        int   c0 = __popc(__ballot_sync(FULL, sp0.w > 0.0f));
        int   c1 = __popc(__ballot_sync(FULL, sp1.w > 0.0f));
        float inv0 = 1.0f / (float)(c0 > 1 ? c0 : 1);
        float inv1 = 1.0f / (float)(c1 > 1 ? c1 : 1);

        float4 z = make_float4(0.f, 0.f, 0.f, 0.f);
        ((float4*)(out + (size_t)n0 * OUT_DIM))[lane] = z;
        ((float4*)(out + (size_t)n1 * OUT_DIM))[lane] = z;

        if (hits0 | hits1) {
#pragma unroll
            for (int s = 0; s < 2; s++) {
                unsigned hh  = s ? hits1 : hits0;
                float    dx  = s ? dx1 : dx0, dy = s ? dy1 : dy0, dz = s ? dz1 : dz0;
                float    r2  = s ? r21 : r20;
                float    inv = s ? inv1 : inv0;
                int      n   = s ? n1 : n0;
                int      idx = s ? idx1 : idx0;
                while (hh) {
                    int p = __ffs(hh) - 1; hh &= hh - 1;
                    float4 kk = skp[p];
                    float  t  = fmaf(dx, kk.x, fmaf(dy, kk.y, fmaf(dz, kk.z, -kk.w)));
                    float  d2 = fmaxf(r2 - t, 0.0f);
                    float  w  = (1.0f - sqrtf(d2) * (1.0f / KP_EXT)) * inv;
                    int slot = atomicAdd(&g_cnt[p], 1);
                    if (slot < HITCAP)
                        g_recs[p][slot] = make_int4(n, idx, __float_as_int(w), 0);
                }
            }
        }
    }

    grid_barrier();

    // ---- phase 3: matvec. tid = h*128 + o; thread caches W[p, h*32+j, o]. ----
    {
        const int p     = blockIdx.x % NKP;
        const int chunk = blockIdx.x / NKP;
        const int nch   = (NBLOCKS - 1 - p) / NKP + 1;
        const int cnt   = min(g_cnt[p], HITCAP);
        const int o     = tid & 127;
        const int h     = tid >> 7;

        if (chunk < cnt) {
            float Wreg[32];
            const float* Wp = wts + (size_t)p * IN_DIM * OUT_DIM
                            + (size_t)(h * 32) * OUT_DIM + o;
#pragma unroll
            for (int j = 0; j < 32; j++) Wreg[j] = Wp[(size_t)j * OUT_DIM];

            for (int i = chunk; i < cnt; i += nch) {
                int4  rec = g_recs[p][i];
                float w   = __int_as_float(rec.z);
                const float4* xr = (const float4*)(x + (size_t)rec.y * IN_DIM + h * 32);
                float a0 = 0.f, a1 = 0.f, a2 = 0.f, a3 = 0.f;
#pragma unroll
                for (int j = 0; j < 8; j++) {
                    float4 v = __ldg(&xr[j]);
                    a0 = fmaf(v.x, Wreg[4 * j + 0], a0);
                    a1 = fmaf(v.y, Wreg[4 * j + 1], a1);
                    a2 = fmaf(v.z, Wreg[4 * j + 2], a2);
                    a3 = fmaf(v.w, Wreg[4 * j + 3], a3);
                }
                atomicAdd(&out[(size_t)rec.x * OUT_DIM + o], w * ((a0 + a1) + (a2 + a3)));
            }
        }
    }
}

extern "C" void kernel_launch(void* const* d_in, const int* in_sizes, int n_in,
                              void* d_out, int out_size) {
    const float* q_pts = (const float*)d_in[0];
    const float* s_pts = (const float*)d_in[1];
    const int*   nidx  = (const int*)  d_in[2];
    const float* x     = (const float*)d_in[3];
    const float* wts   = (const float*)d_in[4];
    const float* kpts  = (const float*)d_in[5];
    float* out = (float*)d_out;

    kpconv_fused<<<NBLOCKS, 256>>>(q_pts, s_pts, nidx, x, wts, kpts, out);
}

// round 6
// speedup vs baseline: 1.2271x; 1.2271x over previous
#include <cuda_runtime.h>
#include <cuda_bf16.h>

// KPConv, sparsity-exact, 3-kernel split (fused version regressed; reverted):
//   K1 pack:   s_pack[s]=(x,y,z,rowsum), 16 rows/warp (MLP=8), kp quads, reset
//   K2 detect: 2 queries per warp -> hit records {n, si, w*inv} binned by p
//   K3 matvec: 64 chunks per p, 256-thr blocks, W[p] half-cached in regs
// Skipping w==0 terms is exact. Shadow row = (1e9,1e9,1e9,0): never hits,
// never valid.

#define N_SUP   40000
#define N_QRY   40000
#define KNBR    32
#define NKP     15
#define IN_DIM  64
#define OUT_DIM 128
#define KP_EXT  0.05f
#define THRESH  (KP_EXT * KP_EXT)
#define HITCAP  65536
#define NBLK    64

__device__ float4 g_spack[N_SUP + 1];
__device__ float4 g_kp4[NKP];          // (2kx, 2ky, 2kz, |kp|^2)
__device__ float  g_R2max;
__device__ int    g_cnt[NKP];
__device__ int4   g_recs[NKP][HITCAP]; // {n, si, w_bits, pad}

// ---------------------------------------------------------------- K1: pack
// 16 rows per warp: 8 independent 512B float4 loads (row pairs), 16-lane
// segmented shuffle reduction -> 2 rowsums per load.
__global__ void __launch_bounds__(256) pack_kernel(const float* __restrict__ x,
                                                   const float* __restrict__ s_pts,
                                                   const float* __restrict__ kpts) {
    if (blockIdx.x == 0) {
        if (threadIdx.x < NKP) g_cnt[threadIdx.x] = 0;
        if (threadIdx.x == 0) {
            g_spack[N_SUP] = make_float4(1e9f, 1e9f, 1e9f, 0.0f);
            float m2 = 0.0f;
            for (int p = 0; p < NKP; p++) {
                float a = kpts[p * 3 + 0], b = kpts[p * 3 + 1], c = kpts[p * 3 + 2];
                float n2 = a * a + b * b + c * c;
                g_kp4[p] = make_float4(2.0f * a, 2.0f * b, 2.0f * c, n2);
                m2 = fmaxf(m2, n2);
            }
            float Rb = sqrtf(m2) + KP_EXT;
            g_R2max = Rb * Rb;
        }
    }

    const unsigned FULL = 0xffffffffu;
    const int warp = (int)((blockIdx.x * blockDim.x + threadIdx.x) >> 5);
    const int lane = threadIdx.x & 31;
    const int base = warp * 16;                      // 2500 warps x 16 rows
    if (base >= N_SUP) return;

    const float4* X4 = (const float4*)x;             // 16 float4 per row

    float s[8];
#pragma unroll
    for (int j = 0; j < 8; j++) {                    // 8 independent 512B loads
        float4 v = X4[(size_t)(base + 2 * j) * 16 + lane];
        s[j] = (v.x + v.y) + (v.z + v.w);
    }
#pragma unroll
    for (int j = 0; j < 8; j++) {
#pragma unroll
        for (int o = 8; o; o >>= 1) s[j] += __shfl_xor_sync(FULL, s[j], o);
        if ((lane & 15) == 0) {                      // lanes 0 and 16 write
            int r = base + 2 * j + (lane >> 4);
            g_spack[r] = make_float4(s_pts[r * 3 + 0], s_pts[r * 3 + 1],
                                     s_pts[r * 3 + 2], s[j]);
        }
    }
}

// -------------------------------------------------------------- K2: detect
// Two queries per warp (identical to the 39.7us baseline).
__global__ void __launch_bounds__(256) detect_kernel(
    const float* __restrict__ q_pts,
    const int*   __restrict__ nidx,
    float*       __restrict__ out)
{
    const unsigned FULL = 0xffffffffu;
    __shared__ float4 skp[NKP];

    const int tid  = threadIdx.x;
    const int lane = tid & 31;
    const int n0   = (int)((blockIdx.x * blockDim.x + tid) >> 5) * 2;
    const int n1   = n0 + 1;

    if (tid < NKP) skp[tid] = g_kp4[tid];
    __syncthreads();

    const int    idx0 = nidx[(size_t)n0 * KNBR + lane];
    const int    idx1 = nidx[(size_t)n1 * KNBR + lane];
    const float4 sp0  = g_spack[idx0];
    const float4 sp1  = g_spack[idx1];

    const float qx0 = q_pts[n0 * 3 + 0], qy0 = q_pts[n0 * 3 + 1], qz0 = q_pts[n0 * 3 + 2];
    const float qx1 = q_pts[n1 * 3 + 0], qy1 = q_pts[n1 * 3 + 1], qz1 = q_pts[n1 * 3 + 2];

    const float R2max = g_R2max;

    const float dx0 = sp0.x - qx0, dy0 = sp0.y - qy0, dz0 = sp0.z - qz0;
    const float dx1 = sp1.x - qx1, dy1 = sp1.y - qy1, dz1 = sp1.z - qz1;
    const float r20 = fmaf(dx0, dx0, fmaf(dy0, dy0, dz0 * dz0));
    const float r21 = fmaf(dx1, dx1, fmaf(dy1, dy1, dz1 * dz1));
    const float rhs0 = r20 - THRESH;
    const float rhs1 = r21 - THRESH;

    unsigned hits0 = 0, hits1 = 0;
    bool any0 = __ballot_sync(FULL, r20 < R2max) != 0;
    bool any1 = __ballot_sync(FULL, r21 < R2max) != 0;
    if (any0 || any1) {
#pragma unroll
        for (int p = 0; p < NKP; p++) {
            float4 kk = skp[p];
            float  t0 = fmaf(dx0, kk.x, fmaf(dy0, kk.y, fmaf(dz0, kk.z, -kk.w)));
            float  t1 = fmaf(dx1, kk.x, fmaf(dy1, kk.y, fmaf(dz1, kk.z, -kk.w)));
            if (t0 > rhs0) hits0 |= (1u << p);
            if (t1 > rhs1) hits1 |= (1u << p);
        }
    }

    int   c0 = __popc(__ballot_sync(FULL, sp0.w > 0.0f));
    int   c1 = __popc(__ballot_sync(FULL, sp1.w > 0.0f));
    float inv0 = 1.0f / (float)(c0 > 1 ? c0 : 1);
    float inv1 = 1.0f / (float)(c1 > 1 ? c1 : 1);

    float4 z = make_float4(0.f, 0.f, 0.f, 0.f);
    ((float4*)(out + (size_t)n0 * OUT_DIM))[lane] = z;
    ((float4*)(out + (size_t)n1 * OUT_DIM))[lane] = z;

    if (hits0 | hits1) {
#pragma unroll
        for (int q = 0; q < 2; q++) {
            unsigned hh  = q ? hits1 : hits0;
            float    dx  = q ? dx1 : dx0, dy = q ? dy1 : dy0, dz = q ? dz1 : dz0;
            float    r2  = q ? r21 : r20;
            float    inv = q ? inv1 : inv0;
            int      n   = q ? n1 : n0;
            int      idx = q ? idx1 : idx0;
            while (hh) {
                int p = __ffs(hh) - 1; hh &= hh - 1;
                float4 kk = skp[p];
                float  t  = fmaf(dx, kk.x, fmaf(dy, kk.y, fmaf(dz, kk.z, -kk.w)));
                float  d2 = fmaxf(r2 - t, 0.0f);
                float  w  = (1.0f - sqrtf(d2) * (1.0f / KP_EXT)) * inv;
                int slot = atomicAdd(&g_cnt[p], 1);
                if (slot < HITCAP)
                    g_recs[p][slot] = make_int4(n, idx, __float_as_int(w), 0);
            }
        }
    }
}

// -------------------------------------------------------------- K3: matvec
// 64 chunks per p; 256 threads: tid = h*128 + o, thread caches
// W[p, h*32 .. h*32+31, o] (32 regs), two halves atomically combined.
__global__ void __launch_bounds__(256) matvec_kernel(
    const float* __restrict__ x,
    const float* __restrict__ wts,
    float*       __restrict__ out)
{
    const int p     = blockIdx.x % NKP;      // 15 * 64 = 960 blocks
    const int chunk = blockIdx.x / NKP;
    const int o     = threadIdx.x & 127;
    const int h     = threadIdx.x >> 7;

    const int cnt = min(g_cnt[p], HITCAP);
    if (chunk >= cnt) return;

    float Wreg[32];
    const float* Wp = wts + (size_t)p * IN_DIM * OUT_DIM + (size_t)(h * 32) * OUT_DIM + o;
#pragma unroll
    for (int j = 0; j < 32; j++) Wreg[j] = Wp[(size_t)j * OUT_DIM];

    for (int i = chunk; i < cnt; i += NBLK) {
        int4  rec = g_recs[p][i];
        float w   = __int_as_float(rec.z);
        const float4* xr = (const float4*)(x + (size_t)rec.y * IN_DIM + h * 32);
        float a0 = 0.f, a1 = 0.f, a2 = 0.f, a3 = 0.f;
#pragma unroll
        for (int j = 0; j < 8; j++) {
            float4 v = __ldg(&xr[j]);
            a0 = fmaf(v.x, Wreg[4 * j + 0], a0);
            a1 = fmaf(v.y, Wreg[4 * j + 1], a1);
            a2 = fmaf(v.z, Wreg[4 * j + 2], a2);
            a3 = fmaf(v.w, Wreg[4 * j + 3], a3);
        }
        atomicAdd(&out[(size_t)rec.x * OUT_DIM + o], w * ((a0 + a1) + (a2 + a3)));
    }
}

extern "C" void kernel_launch(void* const* d_in, const int* in_sizes, int n_in,
                              void* d_out, int out_size) {
    const float* q_pts = (const float*)d_in[0];
    const float* s_pts = (const float*)d_in[1];
    const int*   nidx  = (const int*)  d_in[2];
    const float* x     = (const float*)d_in[3];
    const float* wts   = (const float*)d_in[4];
    const float* kpts  = (const float*)d_in[5];
    float* out = (float*)d_out;

    pack_kernel<<<313, 256>>>(x, s_pts, kpts);        // 2500 warps x 16 rows
    detect_kernel<<<2500, 256>>>(q_pts, nidx, out);   // 20000 warps x 2 queries
    matvec_kernel<<<NKP * NBLK, 256>>>(x, wts, out);  // 960 blocks
}